// round 14
// baseline (speedup 1.0000x reference)
#include <cuda_runtime.h>
#include <cuda_bf16.h>

#define N_NODES 50000
#define HC 32
#define H 64
#define M_PATHS 2
#define E_EDGES 250000
#define P_LEN 3
#define D 256
#define R_TOT (M_PATHS * N_NODES)
#define MLP_TILES 782              // ceil(100000/128)
#define GRID_MLP 148
#define THREADS_MLP 512
#define SMEM_FUSED 131072          // As 64KB + T1s 64KB

__device__ float g_den[R_TOT * 4];      // raw softmax denominators
__device__ float g_a1[N_NODES * 4];
__device__ float g_z[(size_t)R_TOT * D];
__device__ float4 g_fr[M_PATHS * 32];   // per (path, lane): fr0x, fr0y, rb.x, rb.y
__device__ float g_wsum[2];
__device__ float g_beta[2];

// libm celu (used by mlp/a1/combine — keep regalloc there untouched)
__device__ __forceinline__ float celu3f(float x) {
    return x > 0.0f ? x : 3.0f * expm1f(x * (1.0f / 3.0f));
}
// fast celu for pass1 only (MUFU.EX2 path)
__device__ __forceinline__ float celu3f_fast(float x) {
    return x > 0.0f ? x : 3.0f * (__expf(x * (1.0f / 3.0f)) - 1.0f);
}
__device__ __forceinline__ unsigned smem_u32(const void* p) {
    unsigned a;
    asm("{ .reg .u64 t; cvta.to.shared.u64 t, %1; cvt.u32.u64 %0, t; }"
        : "=r"(a) : "l"(p));
    return a;
}
__device__ __forceinline__ unsigned bfpack(float a, float b) {
    __nv_bfloat162 p = __floats2bfloat162_rn(a, b);
    return *reinterpret_cast<unsigned*>(&p);
}
__device__ __forceinline__ void ldmatrix_x4(unsigned* r, unsigned addr) {
    asm volatile("ldmatrix.sync.aligned.m8n8.x4.shared.b16 {%0,%1,%2,%3}, [%4];"
                 : "=r"(r[0]), "=r"(r[1]), "=r"(r[2]), "=r"(r[3]) : "r"(addr));
}
__device__ __forceinline__ void mma_bf16(float* c, const unsigned* a,
                                         const unsigned* b) {
    asm volatile(
        "mma.sync.aligned.m16n8k16.row.col.f32.bf16.bf16.f32 "
        "{%0,%1,%2,%3}, {%4,%5,%6,%7}, {%8,%9}, {%0,%1,%2,%3};"
        : "+f"(c[0]), "+f"(c[1]), "+f"(c[2]), "+f"(c[3])
        : "r"(a[0]), "r"(a[1]), "r"(a[2]), "r"(a[3]), "r"(b[0]), "r"(b[1]));
}

__global__ void zero_all_kernel(const float* __restrict__ r_vec) {
    int i = blockIdx.x * blockDim.x + threadIdx.x;
    if (i < R_TOT * D / 4) ((float4*)g_z)[i] = make_float4(0.f, 0.f, 0.f, 0.f);
    if (i < R_TOT) ((float4*)g_den)[i] = make_float4(0.f, 0.f, 0.f, 0.f);
    if (i < 64) {   // rotation-factor table
        int m = i >> 5, lane = i & 31;
        const float2* rv = (const float2*)r_vec;
        float2 ra = rv[(2 * m) * HC + lane];
        float2 rb = rv[(2 * m + 1) * HC + lane];
        float ia = rsqrtf(ra.x * ra.x + ra.y * ra.y);
        float ib = rsqrtf(rb.x * rb.x + rb.y * rb.y);
        ra.x *= ia; ra.y *= ia; rb.x *= ib; rb.y *= ib;
        g_fr[i] = make_float4(rb.x * ra.x - rb.y * ra.y,
                              rb.x * ra.y + rb.y * ra.x, rb.x, rb.y);
    }
    if (i == 0) { g_wsum[0] = 0.0f; g_wsum[1] = 0.0f; }
}

__global__ void __launch_bounds__(256) a1_kernel(
    const float* __restrict__ features, const float* __restrict__ attn1_w) {
    int warp = threadIdx.x >> 5, lane = threadIdx.x & 31;
    int node = blockIdx.x * 8 + warp;
    if (node >= N_NODES) return;
    float2 f = ((const float2*)features)[node * HC + lane];
    const float2* W1 = (const float2*)attn1_w;
    float r[4];
#pragma unroll
    for (int k = 0; k < 4; k++) {
        float2 w = W1[k * HC + lane];
        r[k] = w.x * f.x + w.y * f.y;
    }
#pragma unroll
    for (int off = 16; off; off >>= 1)
#pragma unroll
        for (int k = 0; k < 4; k++)
            r[k] += __shfl_xor_sync(0xffffffffu, r[k], off);
    if (lane == 0)
#pragma unroll
        for (int k = 0; k < 4; k++) g_a1[node * 4 + k] = celu3f(r[k]);
}

__global__ void __launch_bounds__(256) pass1_kernel(
    const float* __restrict__ features, const float* __restrict__ attn2,
    const int* __restrict__ inst) {
    int warp = threadIdx.x >> 5, lane = threadIdx.x & 31;
    int e = blockIdx.x * 8 + warp;
    int m = blockIdx.y;
    if (e >= E_EDGES) return;
    const int* ip = inst + (size_t)m * E_EDGES * P_LEN + e * 3;

    float4 fr = g_fr[m * 32 + lane];   // fr0x, fr0y, rb.x, rb.y

    int i0 = ip[0], i1 = ip[1], i2 = ip[2];
    const float2* F = (const float2*)features;
    float2 f0 = F[i0 * HC + lane];
    float2 f1 = F[i1 * HC + lane];
    float2 f2 = F[i2 * HC + lane];

    float mre = (f0.x * fr.x - f0.y * fr.y) + (f1.x * fr.z - f1.y * fr.w) + f2.x;
    float mim = (f0.x * fr.y + f0.y * fr.x) + (f1.x * fr.w + f1.y * fr.z) + f2.y;
    mre *= (1.0f / 3.0f); mim *= (1.0f / 3.0f);

    float se0 = celu3f_fast(mre) * __fdividef(1.0f, 1.0f + __expf(-mre));
    float se1 = celu3f_fast(mim) * __fdividef(1.0f, 1.0f + __expf(-mim));
    float ef0 = celu3f_fast(se0), ef1 = celu3f_fast(se1);

    // a2 partials; folded reduction -> lane ends with sum for head (lane&3)
    const float2* W2 = (const float2*)attn2;
    float2 w0 = W2[0 * HC + lane], w1 = W2[1 * HC + lane];
    float2 w2 = W2[2 * HC + lane], w3 = W2[3 * HC + lane];
    float r0 = w0.x * ef0 + w0.y * ef1;
    float r1 = w1.x * ef0 + w1.y * ef1;
    float r2 = w2.x * ef0 + w2.y * ef1;
    float r3 = w3.x * ef0 + w3.y * ef1;
    float tA = __shfl_xor_sync(0xffffffffu, (lane & 1) ? r0 : r1, 1);
    float s01 = ((lane & 1) ? r1 : r0) + tA;
    float tB = __shfl_xor_sync(0xffffffffu, (lane & 1) ? r2 : r3, 1);
    float s23 = ((lane & 1) ? r3 : r2) + tB;
    float tC = __shfl_xor_sync(0xffffffffu, (lane & 2) ? s01 : s23, 2);
    float v = ((lane & 2) ? s23 : s01) + tC;
    v += __shfl_xor_sync(0xffffffffu, v, 4);
    v += __shfl_xor_sync(0xffffffffu, v, 8);
    v += __shfl_xor_sync(0xffffffffu, v, 16);

    float4 a1v = *(const float4*)(g_a1 + (size_t)i0 * 4);
    int hk = lane & 3;
    float a1h = hk == 0 ? a1v.x : hk == 1 ? a1v.y : hk == 2 ? a1v.z : a1v.w;
    float exval = __expf(celu3f_fast(a1h + v));  // logits bounded; exp safe

    size_t rowg = (size_t)m * N_NODES + i0;
    if (lane < 4) atomicAdd(g_den + rowg * 4 + lane, exval);

    int k0 = (lane & 1) * 2;
    int base4 = lane & 28;
    float exa = __shfl_sync(0xffffffffu, exval, base4 | k0);
    float exb = __shfl_sync(0xffffffffu, exval, base4 | (k0 + 1));

    float p0 = __shfl_xor_sync(0xffffffffu, ef0, 1);
    float p1 = __shfl_xor_sync(0xffffffffu, ef1, 1);
    float v0, v1, v2, v3;
    if ((lane & 1) == 0) { v0 = ef0; v1 = ef1; v2 = p0; v3 = p1; }
    else                 { v0 = p0;  v1 = p1;  v2 = ef0; v3 = ef1; }
    int g4 = (lane >> 1) * 4;

    float* base = g_z + rowg * D;
    float* pa = base + k0 * H + g4;
    float* pb = base + (k0 + 1) * H + g4;
    asm volatile("red.global.add.v4.f32 [%0], {%1,%2,%3,%4};" ::
                 "l"(pa), "f"(exa * v0), "f"(exa * v1),
                 "f"(exa * v2), "f"(exa * v3) : "memory");
    asm volatile("red.global.add.v4.f32 [%0], {%1,%2,%3,%4};" ::
                 "l"(pb), "f"(exb * v0), "f"(exb * v1),
                 "f"(exb * v2), "f"(exb * v3) : "memory");
}

// ---- Fused MLP: L1+L2+L3 with bf16 mma.sync --------------------------------
// B1 fragments persistent; B2 fragments reloaded per tile (peak regs <= 128,
// no spills). recip folded into staging (reads raw den).
__global__ void __launch_bounds__(THREADS_MLP, 1) mlp_fused(
    const float* __restrict__ fw1, const float* __restrict__ fb1,
    const float* __restrict__ fw2, const float* __restrict__ fb2,
    const float* __restrict__ fw3) {
    extern __shared__ char smem[];
    const unsigned sbA = smem_u32(smem);
    const unsigned sbT = sbA + 65536;
    int tid = threadIdx.x, w = tid >> 5, l = tid & 31;
    int lq = l >> 2, lr = l & 3;

    unsigned B1[2][16][2];
#pragma unroll
    for (int nt = 0; nt < 2; nt++) {
        int col = w * 16 + nt * 8 + lq;
#pragma unroll
        for (int kt = 0; kt < 16; kt++) {
            const float* p = fw1 + (size_t)col * 256 + kt * 16 + lr * 2;
            B1[nt][kt][0] = bfpack(p[0], p[1]);
            B1[nt][kt][1] = bfpack(p[8], p[9]);
        }
    }
    float fb1c[2][2], fb2c[2], fw3c[2];
#pragma unroll
    for (int nt = 0; nt < 2; nt++) {
        fb1c[nt][0] = fb1[w * 16 + nt * 8 + lr * 2];
        fb1c[nt][1] = fb1[w * 16 + nt * 8 + lr * 2 + 1];
    }
    fb2c[0] = fb2[w * 8 + lr * 2];     fb2c[1] = fb2[w * 8 + lr * 2 + 1];
    fw3c[0] = fw3[w * 8 + lr * 2];     fw3c[1] = fw3[w * 8 + lr * 2 + 1];
    const float* fw2base = fw2 + (size_t)(w * 8 + lq) * 256 + lr * 2;

    float vs0 = 0.0f, vs1 = 0.0f;

    for (int t = blockIdx.x; t < MLP_TILES; t += GRID_MLP) {
        int r0 = t * 128;
#pragma unroll
        for (int i = tid; i < 4096; i += THREADS_MLP) {
            int r = i >> 5, c = i & 31;
            int gr = r0 + r;
            unsigned off = r * 512 + ((unsigned)(c ^ (r & 7)) << 4);
            uint4 pk = make_uint4(0u, 0u, 0u, 0u);
            if (gr < R_TOT) {
                float d = g_den[(size_t)gr * 4 + (c >> 3)];
                float inv = d > 0.0f ? 1.0f / d : 0.0f;   // == old recip
                const float4* zp = (const float4*)(g_z + (size_t)gr * 256 + c * 8);
                float4 za = zp[0], zb = zp[1];
                pk = make_uint4(
                    bfpack(celu3f(za.x * inv), celu3f(za.y * inv)),
                    bfpack(celu3f(za.z * inv), celu3f(za.w * inv)),
                    bfpack(celu3f(zb.x * inv), celu3f(zb.y * inv)),
                    bfpack(celu3f(zb.z * inv), celu3f(zb.w * inv)));
            }
            *(uint4*)(smem + off) = pk;
        }
        __syncthreads();

#pragma unroll 2
        for (int mt = 0; mt < 8; mt++) {
            int m0 = mt * 16;
            float acc[2][4] = {{0.f, 0.f, 0.f, 0.f}, {0.f, 0.f, 0.f, 0.f}};
            int arow = m0 + (l & 15);
#pragma unroll
            for (int kt = 0; kt < 16; kt++) {
                unsigned a[4];
                unsigned ad = sbA + arow * 512 +
                              ((unsigned)((2 * kt + (l >> 4)) ^ (arow & 7)) << 4);
                ldmatrix_x4(a, ad);
                mma_bf16(acc[0], a, B1[0][kt]);
                mma_bf16(acc[1], a, B1[1][kt]);
            }
            int rlo = m0 + lq, rhi = rlo + 8;
#pragma unroll
            for (int nt = 0; nt < 2; nt++) {
                int col = w * 16 + nt * 8 + lr * 2;
                unsigned clo = bfpack(celu3f(acc[nt][0] + fb1c[nt][0]),
                                      celu3f(acc[nt][1] + fb1c[nt][1]));
                unsigned chi = bfpack(celu3f(acc[nt][2] + fb1c[nt][0]),
                                      celu3f(acc[nt][3] + fb1c[nt][1]));
                unsigned olo = 65536 + rlo * 512 +
                               ((unsigned)((col >> 3) ^ (rlo & 7)) << 4) + (col & 7) * 2;
                unsigned ohi = 65536 + rhi * 512 +
                               ((unsigned)((col >> 3) ^ (rhi & 7)) << 4) + (col & 7) * 2;
                *(unsigned*)(smem + olo) = clo;
                *(unsigned*)(smem + ohi) = chi;
            }
        }
        __syncthreads();

        // B2 fragments: transient per tile (keeps peak registers <= 128)
        unsigned B2[16][2];
#pragma unroll
        for (int kt = 0; kt < 16; kt++) {
            const float* p = fw2base + kt * 16;
            B2[kt][0] = bfpack(p[0], p[1]);
            B2[kt][1] = bfpack(p[8], p[9]);
        }

#pragma unroll 2
        for (int mt = 0; mt < 8; mt++) {
            int m0 = mt * 16;
            float acc[4] = {0.f, 0.f, 0.f, 0.f};
            int arow = m0 + (l & 15);
#pragma unroll
            for (int kt = 0; kt < 16; kt++) {
                unsigned a[4];
                unsigned ad = sbT + arow * 512 +
                              ((unsigned)((2 * kt + (l >> 4)) ^ (arow & 7)) << 4);
                ldmatrix_x4(a, ad);
                mma_bf16(acc, a, B2[kt]);
            }
            int rlo = r0 + m0 + lq, rhi = rlo + 8;
            float slo = celu3f(acc[0] + fb2c[0]) * fw3c[0] +
                        celu3f(acc[1] + fb2c[1]) * fw3c[1];
            float shi = celu3f(acc[2] + fb2c[0]) * fw3c[0] +
                        celu3f(acc[3] + fb2c[1]) * fw3c[1];
            if (rlo < N_NODES) vs0 += slo; else if (rlo < R_TOT) vs1 += slo;
            if (rhi < N_NODES) vs0 += shi; else if (rhi < R_TOT) vs1 += shi;
        }
    }

#pragma unroll
    for (int off = 16; off; off >>= 1) {
        vs0 += __shfl_xor_sync(0xffffffffu, vs0, off);
        vs1 += __shfl_xor_sync(0xffffffffu, vs1, off);
    }
    __syncthreads();
    float* red = (float*)smem;
    if (l == 0) { red[w] = vs0; red[16 + w] = vs1; }
    __syncthreads();
    if (tid == 0) {
        float a0 = 0.f, a1 = 0.f;
#pragma unroll
        for (int i = 0; i < 16; i++) { a0 += red[i]; a1 += red[16 + i]; }
        atomicAdd(&g_wsum[0], a0);
        atomicAdd(&g_wsum[1], a1);
    }
}

__global__ void beta_kernel() {
    float w0 = g_wsum[0] * (1.0f / (float)N_NODES);
    float w1 = g_wsum[1] * (1.0f / (float)N_NODES);
    float mx = fmaxf(w0, w1);
    float e0 = expf(w0 - mx), e1 = expf(w1 - mx);
    float inv = 1.0f / (e0 + e1);
    g_beta[0] = e0 * inv;
    g_beta[1] = e1 * inv;
}

__global__ void combine_kernel(float* __restrict__ out) {
    int i = blockIdx.x * blockDim.x + threadIdx.x;
    if (i < N_NODES * D / 4) {
        int f = i * 4;
        int node = f >> 8;
        int head = (f & 255) >> 6;
        float d0 = g_den[(size_t)node * 4 + head];
        float d1 = g_den[(size_t)(N_NODES + node) * 4 + head];
        float inv0 = d0 > 0.0f ? 1.0f / d0 : 0.0f;
        float inv1 = d1 > 0.0f ? 1.0f / d1 : 0.0f;
        float b0 = g_beta[0], b1 = g_beta[1];
        float4 a = ((const float4*)g_z)[i];
        float4 c = ((const float4*)(g_z + (size_t)N_NODES * D))[i];
        float4 o;
        o.x = b0 * celu3f(a.x * inv0) + b1 * celu3f(c.x * inv1);
        o.y = b0 * celu3f(a.y * inv0) + b1 * celu3f(c.y * inv1);
        o.z = b0 * celu3f(a.z * inv0) + b1 * celu3f(c.z * inv1);
        o.w = b0 * celu3f(a.w * inv0) + b1 * celu3f(c.w * inv1);
        ((float4*)out)[i] = o;
    }
}

extern "C" void kernel_launch(void* const* d_in, const int* in_sizes, int n_in,
                              void* d_out, int out_size) {
    const float* features = (const float*)d_in[0];
    const float* r_vec    = (const float*)d_in[1];
    const float* attn1_w  = (const float*)d_in[2];
    const float* attn2    = (const float*)d_in[3];
    const float* fw1      = (const float*)d_in[4];
    const float* fb1      = (const float*)d_in[5];
    const float* fw2      = (const float*)d_in[6];
    const float* fb2      = (const float*)d_in[7];
    const float* fw3      = (const float*)d_in[8];
    const int*   inst     = (const int*)d_in[9];
    float* out = (float*)d_out;

    cudaFuncSetAttribute(mlp_fused,
                         cudaFuncAttributeMaxDynamicSharedMemorySize, SMEM_FUSED);

    zero_all_kernel<<<(R_TOT * D / 4 + 255) / 256, 256>>>(r_vec);   // 1
    a1_kernel<<<(N_NODES + 7) / 8, 256>>>(features, attn1_w);       // 2
    pass1_kernel<<<dim3(E_EDGES / 8, 2), 256>>>(features, attn2, inst); // 3
    mlp_fused<<<GRID_MLP, THREADS_MLP, SMEM_FUSED>>>(fw1, fb1, fw2, fb2, fw3); // 4 (ncu)
    beta_kernel<<<1, 1>>>();                                        // 5
    combine_kernel<<<(N_NODES * D / 4 + 255) / 256, 256>>>(out);    // 6
}

// round 15
// speedup vs baseline: 1.6677x; 1.6677x over previous
#include <cuda_runtime.h>
#include <cuda_bf16.h>

#define N_NODES 50000
#define HC 32
#define H 64
#define M_PATHS 2
#define E_EDGES 250000
#define P_LEN 3
#define D 256
#define R_TOT (M_PATHS * N_NODES)
#define MLP_TILES 782              // ceil(100000/128)
#define GRID_MLP 148
#define THREADS_MLP 512
#define SMEM_FUSED 131072          // As 64KB + T1s 64KB

__device__ float g_den[R_TOT * 4];      // raw softmax denominators
__device__ float g_a1[N_NODES * 4];
__device__ float g_z[(size_t)R_TOT * D];
__device__ __nv_bfloat16 g_zc[(size_t)R_TOT * D];  // celu3(z*inv) in bf16
__device__ float4 g_fr[M_PATHS * 32];
__device__ float g_wsum[2];
__device__ float g_beta[2];

// libm celu (mlp epilogues / combine — keep proven regalloc)
__device__ __forceinline__ float celu3f(float x) {
    return x > 0.0f ? x : 3.0f * expm1f(x * (1.0f / 3.0f));
}
// fast celu (pass1 + zc: MUFU.EX2 path)
__device__ __forceinline__ float celu3f_fast(float x) {
    return x > 0.0f ? x : 3.0f * (__expf(x * (1.0f / 3.0f)) - 1.0f);
}
__device__ __forceinline__ unsigned smem_u32(const void* p) {
    unsigned a;
    asm("{ .reg .u64 t; cvta.to.shared.u64 t, %1; cvt.u32.u64 %0, t; }"
        : "=r"(a) : "l"(p));
    return a;
}
__device__ __forceinline__ unsigned bfpack(float a, float b) {
    __nv_bfloat162 p = __floats2bfloat162_rn(a, b);
    return *reinterpret_cast<unsigned*>(&p);
}
__device__ __forceinline__ void ldmatrix_x4(unsigned* r, unsigned addr) {
    asm volatile("ldmatrix.sync.aligned.m8n8.x4.shared.b16 {%0,%1,%2,%3}, [%4];"
                 : "=r"(r[0]), "=r"(r[1]), "=r"(r[2]), "=r"(r[3]) : "r"(addr));
}
__device__ __forceinline__ void mma_bf16(float* c, const unsigned* a,
                                         const unsigned* b) {
    asm volatile(
        "mma.sync.aligned.m16n8k16.row.col.f32.bf16.bf16.f32 "
        "{%0,%1,%2,%3}, {%4,%5,%6,%7}, {%8,%9}, {%0,%1,%2,%3};"
        : "+f"(c[0]), "+f"(c[1]), "+f"(c[2]), "+f"(c[3])
        : "r"(a[0]), "r"(a[1]), "r"(a[2]), "r"(a[3]), "r"(b[0]), "r"(b[1]));
}

// ---- prep: zero z/den/wsum + fr table + a1 (merged to keep mlp at launch 4)
__global__ void __launch_bounds__(256) prep_kernel(
    const float* __restrict__ r_vec, const float* __restrict__ features,
    const float* __restrict__ attn1_w) {
    int i = blockIdx.x * blockDim.x + threadIdx.x;
    if (i < R_TOT * D / 4) ((float4*)g_z)[i] = make_float4(0.f, 0.f, 0.f, 0.f);
    if (i < R_TOT) ((float4*)g_den)[i] = make_float4(0.f, 0.f, 0.f, 0.f);
    if (i < 64) {
        int m = i >> 5, lane = i & 31;
        const float2* rv = (const float2*)r_vec;
        float2 ra = rv[(2 * m) * HC + lane];
        float2 rb = rv[(2 * m + 1) * HC + lane];
        float ia = rsqrtf(ra.x * ra.x + ra.y * ra.y);
        float ib = rsqrtf(rb.x * rb.x + rb.y * rb.y);
        ra.x *= ia; ra.y *= ia; rb.x *= ib; rb.y *= ib;
        g_fr[i] = make_float4(rb.x * ra.x - rb.y * ra.y,
                              rb.x * ra.y + rb.y * ra.x, rb.x, rb.y);
    }
    if (i == 0) { g_wsum[0] = 0.0f; g_wsum[1] = 0.0f; }

    // a1 = celu3(features @ attn1_w.T), one warp per node (warp-uniform branch)
    int warp = threadIdx.x >> 5, lane = threadIdx.x & 31;
    int node = blockIdx.x * 8 + warp;
    if (node < N_NODES) {
        float2 f = ((const float2*)features)[node * HC + lane];
        const float2* W1 = (const float2*)attn1_w;
        float r[4];
#pragma unroll
        for (int k = 0; k < 4; k++) {
            float2 w = W1[k * HC + lane];
            r[k] = w.x * f.x + w.y * f.y;
        }
#pragma unroll
        for (int off = 16; off; off >>= 1)
#pragma unroll
            for (int k = 0; k < 4; k++)
                r[k] += __shfl_xor_sync(0xffffffffu, r[k], off);
        if (lane == 0)
#pragma unroll
            for (int k = 0; k < 4; k++) g_a1[node * 4 + k] = celu3f(r[k]);
    }
}

__global__ void __launch_bounds__(256) pass1_kernel(
    const float* __restrict__ features, const float* __restrict__ attn2,
    const int* __restrict__ inst) {
    int warp = threadIdx.x >> 5, lane = threadIdx.x & 31;
    int e = blockIdx.x * 8 + warp;
    int m = blockIdx.y;
    if (e >= E_EDGES) return;
    const int* ip = inst + (size_t)m * E_EDGES * P_LEN + e * 3;

    float4 fr = g_fr[m * 32 + lane];

    int i0 = ip[0], i1 = ip[1], i2 = ip[2];
    const float2* F = (const float2*)features;
    float2 f0 = F[i0 * HC + lane];
    float2 f1 = F[i1 * HC + lane];
    float2 f2 = F[i2 * HC + lane];

    float mre = (f0.x * fr.x - f0.y * fr.y) + (f1.x * fr.z - f1.y * fr.w) + f2.x;
    float mim = (f0.x * fr.y + f0.y * fr.x) + (f1.x * fr.w + f1.y * fr.z) + f2.y;
    mre *= (1.0f / 3.0f); mim *= (1.0f / 3.0f);

    float se0 = celu3f_fast(mre) * __fdividef(1.0f, 1.0f + __expf(-mre));
    float se1 = celu3f_fast(mim) * __fdividef(1.0f, 1.0f + __expf(-mim));
    float ef0 = celu3f_fast(se0), ef1 = celu3f_fast(se1);

    const float2* W2 = (const float2*)attn2;
    float2 w0 = W2[0 * HC + lane], w1 = W2[1 * HC + lane];
    float2 w2 = W2[2 * HC + lane], w3 = W2[3 * HC + lane];
    float r0 = w0.x * ef0 + w0.y * ef1;
    float r1 = w1.x * ef0 + w1.y * ef1;
    float r2 = w2.x * ef0 + w2.y * ef1;
    float r3 = w3.x * ef0 + w3.y * ef1;
    float tA = __shfl_xor_sync(0xffffffffu, (lane & 1) ? r0 : r1, 1);
    float s01 = ((lane & 1) ? r1 : r0) + tA;
    float tB = __shfl_xor_sync(0xffffffffu, (lane & 1) ? r2 : r3, 1);
    float s23 = ((lane & 1) ? r3 : r2) + tB;
    float tC = __shfl_xor_sync(0xffffffffu, (lane & 2) ? s01 : s23, 2);
    float v = ((lane & 2) ? s23 : s01) + tC;
    v += __shfl_xor_sync(0xffffffffu, v, 4);
    v += __shfl_xor_sync(0xffffffffu, v, 8);
    v += __shfl_xor_sync(0xffffffffu, v, 16);

    float4 a1v = *(const float4*)(g_a1 + (size_t)i0 * 4);
    int hk = lane & 3;
    float a1h = hk == 0 ? a1v.x : hk == 1 ? a1v.y : hk == 2 ? a1v.z : a1v.w;
    float exval = __expf(celu3f_fast(a1h + v));

    size_t rowg = (size_t)m * N_NODES + i0;
    if (lane < 4) atomicAdd(g_den + rowg * 4 + lane, exval);

    int k0 = (lane & 1) * 2;
    int base4 = lane & 28;
    float exa = __shfl_sync(0xffffffffu, exval, base4 | k0);
    float exb = __shfl_sync(0xffffffffu, exval, base4 | (k0 + 1));

    float p0 = __shfl_xor_sync(0xffffffffu, ef0, 1);
    float p1 = __shfl_xor_sync(0xffffffffu, ef1, 1);
    float v0, v1, v2, v3;
    if ((lane & 1) == 0) { v0 = ef0; v1 = ef1; v2 = p0; v3 = p1; }
    else                 { v0 = p0;  v1 = p1;  v2 = ef0; v3 = ef1; }
    int g4 = (lane >> 1) * 4;

    float* base = g_z + rowg * D;
    float* pa = base + k0 * H + g4;
    float* pb = base + (k0 + 1) * H + g4;
    asm volatile("red.global.add.v4.f32 [%0], {%1,%2,%3,%4};" ::
                 "l"(pa), "f"(exa * v0), "f"(exa * v1),
                 "f"(exa * v2), "f"(exa * v3) : "memory");
    asm volatile("red.global.add.v4.f32 [%0], {%1,%2,%3,%4};" ::
                 "l"(pb), "f"(exb * v0), "f"(exb * v1),
                 "f"(exb * v2), "f"(exb * v3) : "memory");
}

// ---- zc = bf16(celu3(z * inv_den)) at full occupancy ------------------------
__global__ void __launch_bounds__(256) zc_kernel() {
    int i = blockIdx.x * blockDim.x + threadIdx.x;   // 16B chunk index
    if (i >= R_TOT * 32) return;
    int row = i >> 5, c = i & 31;
    float d = g_den[(size_t)row * 4 + (c >> 3)];
    float inv = d > 0.0f ? 1.0f / d : 0.0f;
    const float4* zp = (const float4*)(g_z + (size_t)row * 256 + c * 8);
    float4 za = zp[0], zb = zp[1];
    uint4 pk = make_uint4(
        bfpack(celu3f_fast(za.x * inv), celu3f_fast(za.y * inv)),
        bfpack(celu3f_fast(za.z * inv), celu3f_fast(za.w * inv)),
        bfpack(celu3f_fast(zb.x * inv), celu3f_fast(zb.y * inv)),
        bfpack(celu3f_fast(zb.z * inv), celu3f_fast(zb.w * inv)));
    *(uint4*)(g_zc + (size_t)row * 256 + c * 8) = pk;
}

// ---- Fused MLP: staging = pure swizzled copy of zc; B1+B2 persistent -------
__global__ void __launch_bounds__(THREADS_MLP, 1) mlp_fused(
    const float* __restrict__ fw1, const float* __restrict__ fb1,
    const float* __restrict__ fw2, const float* __restrict__ fb2,
    const float* __restrict__ fw3) {
    extern __shared__ char smem[];
    const unsigned sbA = smem_u32(smem);
    const unsigned sbT = sbA + 65536;
    int tid = threadIdx.x, w = tid >> 5, l = tid & 31;
    int lq = l >> 2, lr = l & 3;

    unsigned B1[2][16][2];
#pragma unroll
    for (int nt = 0; nt < 2; nt++) {
        int col = w * 16 + nt * 8 + lq;
#pragma unroll
        for (int kt = 0; kt < 16; kt++) {
            const float* p = fw1 + (size_t)col * 256 + kt * 16 + lr * 2;
            B1[nt][kt][0] = bfpack(p[0], p[1]);
            B1[nt][kt][1] = bfpack(p[8], p[9]);
        }
    }
    unsigned B2[16][2];
    {
        int col = w * 8 + lq;
#pragma unroll
        for (int kt = 0; kt < 16; kt++) {
            const float* p = fw2 + (size_t)col * 256 + kt * 16 + lr * 2;
            B2[kt][0] = bfpack(p[0], p[1]);
            B2[kt][1] = bfpack(p[8], p[9]);
        }
    }
    float fb1c[2][2], fb2c[2], fw3c[2];
#pragma unroll
    for (int nt = 0; nt < 2; nt++) {
        fb1c[nt][0] = fb1[w * 16 + nt * 8 + lr * 2];
        fb1c[nt][1] = fb1[w * 16 + nt * 8 + lr * 2 + 1];
    }
    fb2c[0] = fb2[w * 8 + lr * 2];     fb2c[1] = fb2[w * 8 + lr * 2 + 1];
    fw3c[0] = fw3[w * 8 + lr * 2];     fw3c[1] = fw3[w * 8 + lr * 2 + 1];

    float vs0 = 0.0f, vs1 = 0.0f;

    for (int t = blockIdx.x; t < MLP_TILES; t += GRID_MLP) {
        int r0 = t * 128;
        // staging: swizzled bf16 copy (no celu, no div)
#pragma unroll
        for (int i = tid; i < 4096; i += THREADS_MLP) {
            int r = i >> 5, c = i & 31;
            int gr = r0 + r;
            unsigned off = r * 512 + ((unsigned)(c ^ (r & 7)) << 4);
            uint4 pk = (gr < R_TOT)
                ? *(const uint4*)(g_zc + (size_t)gr * 256 + c * 8)
                : make_uint4(0u, 0u, 0u, 0u);
            *(uint4*)(smem + off) = pk;
        }
        __syncthreads();

#pragma unroll 2
        for (int mt = 0; mt < 8; mt++) {
            int m0 = mt * 16;
            float acc[2][4] = {{0.f, 0.f, 0.f, 0.f}, {0.f, 0.f, 0.f, 0.f}};
            int arow = m0 + (l & 15);
#pragma unroll
            for (int kt = 0; kt < 16; kt++) {
                unsigned a[4];
                unsigned ad = sbA + arow * 512 +
                              ((unsigned)((2 * kt + (l >> 4)) ^ (arow & 7)) << 4);
                ldmatrix_x4(a, ad);
                mma_bf16(acc[0], a, B1[0][kt]);
                mma_bf16(acc[1], a, B1[1][kt]);
            }
            int rlo = m0 + lq, rhi = rlo + 8;
#pragma unroll
            for (int nt = 0; nt < 2; nt++) {
                int col = w * 16 + nt * 8 + lr * 2;
                unsigned clo = bfpack(celu3f(acc[nt][0] + fb1c[nt][0]),
                                      celu3f(acc[nt][1] + fb1c[nt][1]));
                unsigned chi = bfpack(celu3f(acc[nt][2] + fb1c[nt][0]),
                                      celu3f(acc[nt][3] + fb1c[nt][1]));
                unsigned olo = 65536 + rlo * 512 +
                               ((unsigned)((col >> 3) ^ (rlo & 7)) << 4) + (col & 7) * 2;
                unsigned ohi = 65536 + rhi * 512 +
                               ((unsigned)((col >> 3) ^ (rhi & 7)) << 4) + (col & 7) * 2;
                *(unsigned*)(smem + olo) = clo;
                *(unsigned*)(smem + ohi) = chi;
            }
        }
        __syncthreads();

#pragma unroll 2
        for (int mt = 0; mt < 8; mt++) {
            int m0 = mt * 16;
            float acc[4] = {0.f, 0.f, 0.f, 0.f};
            int arow = m0 + (l & 15);
#pragma unroll
            for (int kt = 0; kt < 16; kt++) {
                unsigned a[4];
                unsigned ad = sbT + arow * 512 +
                              ((unsigned)((2 * kt + (l >> 4)) ^ (arow & 7)) << 4);
                ldmatrix_x4(a, ad);
                mma_bf16(acc, a, B2[kt]);
            }
            int rlo = r0 + m0 + lq, rhi = rlo + 8;
            float slo = celu3f(acc[0] + fb2c[0]) * fw3c[0] +
                        celu3f(acc[1] + fb2c[1]) * fw3c[1];
            float shi = celu3f(acc[2] + fb2c[0]) * fw3c[0] +
                        celu3f(acc[3] + fb2c[1]) * fw3c[1];
            if (rlo < N_NODES) vs0 += slo; else if (rlo < R_TOT) vs1 += slo;
            if (rhi < N_NODES) vs0 += shi; else if (rhi < R_TOT) vs1 += shi;
        }
    }

#pragma unroll
    for (int off = 16; off; off >>= 1) {
        vs0 += __shfl_xor_sync(0xffffffffu, vs0, off);
        vs1 += __shfl_xor_sync(0xffffffffu, vs1, off);
    }
    __syncthreads();
    float* red = (float*)smem;
    if (l == 0) { red[w] = vs0; red[16 + w] = vs1; }
    __syncthreads();
    if (tid == 0) {
        float a0 = 0.f, a1 = 0.f;
#pragma unroll
        for (int i = 0; i < 16; i++) { a0 += red[i]; a1 += red[16 + i]; }
        atomicAdd(&g_wsum[0], a0);
        atomicAdd(&g_wsum[1], a1);
    }
}

__global__ void beta_kernel() {
    float w0 = g_wsum[0] * (1.0f / (float)N_NODES);
    float w1 = g_wsum[1] * (1.0f / (float)N_NODES);
    float mx = fmaxf(w0, w1);
    float e0 = expf(w0 - mx), e1 = expf(w1 - mx);
    float inv = 1.0f / (e0 + e1);
    g_beta[0] = e0 * inv;
    g_beta[1] = e1 * inv;
}

__global__ void combine_kernel(float* __restrict__ out) {
    int i = blockIdx.x * blockDim.x + threadIdx.x;
    if (i < N_NODES * D / 4) {
        int f = i * 4;
        int node = f >> 8;
        int head = (f & 255) >> 6;
        float d0 = g_den[(size_t)node * 4 + head];
        float d1 = g_den[(size_t)(N_NODES + node) * 4 + head];
        float inv0 = d0 > 0.0f ? 1.0f / d0 : 0.0f;
        float inv1 = d1 > 0.0f ? 1.0f / d1 : 0.0f;
        float b0 = g_beta[0], b1 = g_beta[1];
        float4 a = ((const float4*)g_z)[i];
        float4 c = ((const float4*)(g_z + (size_t)N_NODES * D))[i];
        float4 o;
        o.x = b0 * celu3f(a.x * inv0) + b1 * celu3f(c.x * inv1);
        o.y = b0 * celu3f(a.y * inv0) + b1 * celu3f(c.y * inv1);
        o.z = b0 * celu3f(a.z * inv0) + b1 * celu3f(c.z * inv1);
        o.w = b0 * celu3f(a.w * inv0) + b1 * celu3f(c.w * inv1);
        ((float4*)out)[i] = o;
    }
}

extern "C" void kernel_launch(void* const* d_in, const int* in_sizes, int n_in,
                              void* d_out, int out_size) {
    const float* features = (const float*)d_in[0];
    const float* r_vec    = (const float*)d_in[1];
    const float* attn1_w  = (const float*)d_in[2];
    const float* attn2    = (const float*)d_in[3];
    const float* fw1      = (const float*)d_in[4];
    const float* fb1      = (const float*)d_in[5];
    const float* fw2      = (const float*)d_in[6];
    const float* fb2      = (const float*)d_in[7];
    const float* fw3      = (const float*)d_in[8];
    const int*   inst     = (const int*)d_in[9];
    float* out = (float*)d_out;

    cudaFuncSetAttribute(mlp_fused,
                         cudaFuncAttributeMaxDynamicSharedMemorySize, SMEM_FUSED);

    prep_kernel<<<(R_TOT * D / 4 + 255) / 256, 256>>>(r_vec, features, attn1_w); // 1
    pass1_kernel<<<dim3(E_EDGES / 8, 2), 256>>>(features, attn2, inst);          // 2
    zc_kernel<<<(R_TOT * 32 + 255) / 256, 256>>>();                              // 3
    mlp_fused<<<GRID_MLP, THREADS_MLP, SMEM_FUSED>>>(fw1, fb1, fw2, fb2, fw3);   // 4 (ncu)
    beta_kernel<<<1, 1>>>();                                                     // 5
    combine_kernel<<<(N_NODES * D / 4 + 255) / 256, 256>>>(out);                 // 6
}

// round 16
// speedup vs baseline: 1.8962x; 1.1370x over previous
#include <cuda_runtime.h>
#include <cuda_bf16.h>

#define N_NODES 50000
#define HC 32
#define H 64
#define M_PATHS 2
#define E_EDGES 250000
#define P_LEN 3
#define D 256
#define R_TOT (M_PATHS * N_NODES)
#define MLP_TILES 782              // ceil(100000/128)
#define GRID_MLP 148
#define THREADS_MLP 512
#define SMEM_FUSED 196608          // As0 64KB + As1 64KB + T1s 64KB

__device__ float g_den[R_TOT * 4];      // raw softmax denominators
__device__ float g_a1[N_NODES * 4];
__device__ float g_z[(size_t)R_TOT * D];
__device__ __nv_bfloat16 g_zc[(size_t)R_TOT * D];  // celu3(z*inv) in bf16
__device__ float4 g_fr[M_PATHS * 32];
__device__ float g_wsum[2];
__device__ float g_beta[2];

// libm celu (prep only)
__device__ __forceinline__ float celu3f(float x) {
    return x > 0.0f ? x : 3.0f * expm1f(x * (1.0f / 3.0f));
}
// fast celu (MUFU.EX2 path)
__device__ __forceinline__ float celu3f_fast(float x) {
    return x > 0.0f ? x : 3.0f * (__expf(x * (1.0f / 3.0f)) - 1.0f);
}
__device__ __forceinline__ unsigned smem_u32(const void* p) {
    unsigned a;
    asm("{ .reg .u64 t; cvta.to.shared.u64 t, %1; cvt.u32.u64 %0, t; }"
        : "=r"(a) : "l"(p));
    return a;
}
__device__ __forceinline__ unsigned bfpack(float a, float b) {
    __nv_bfloat162 p = __floats2bfloat162_rn(a, b);
    return *reinterpret_cast<unsigned*>(&p);
}
__device__ __forceinline__ void ldmatrix_x4(unsigned* r, unsigned addr) {
    asm volatile("ldmatrix.sync.aligned.m8n8.x4.shared.b16 {%0,%1,%2,%3}, [%4];"
                 : "=r"(r[0]), "=r"(r[1]), "=r"(r[2]), "=r"(r[3]) : "r"(addr));
}
__device__ __forceinline__ void mma_bf16(float* c, const unsigned* a,
                                         const unsigned* b) {
    asm volatile(
        "mma.sync.aligned.m16n8k16.row.col.f32.bf16.bf16.f32 "
        "{%0,%1,%2,%3}, {%4,%5,%6,%7}, {%8,%9}, {%0,%1,%2,%3};"
        : "+f"(c[0]), "+f"(c[1]), "+f"(c[2]), "+f"(c[3])
        : "r"(a[0]), "r"(a[1]), "r"(a[2]), "r"(a[3]), "r"(b[0]), "r"(b[1]));
}
__device__ __forceinline__ void cp_async16(unsigned dst, const void* src,
                                           unsigned sz) {
    asm volatile("cp.async.cg.shared.global [%0], [%1], 16, %2;"
                 :: "r"(dst), "l"(src), "r"(sz) : "memory");
}

// ---- prep: zero z/den/wsum + fr table + a1 ---------------------------------
__global__ void __launch_bounds__(256) prep_kernel(
    const float* __restrict__ r_vec, const float* __restrict__ features,
    const float* __restrict__ attn1_w) {
    int i = blockIdx.x * blockDim.x + threadIdx.x;
    if (i < R_TOT * D / 4) ((float4*)g_z)[i] = make_float4(0.f, 0.f, 0.f, 0.f);
    if (i < R_TOT) ((float4*)g_den)[i] = make_float4(0.f, 0.f, 0.f, 0.f);
    if (i < 64) {
        int m = i >> 5, lane = i & 31;
        const float2* rv = (const float2*)r_vec;
        float2 ra = rv[(2 * m) * HC + lane];
        float2 rb = rv[(2 * m + 1) * HC + lane];
        float ia = rsqrtf(ra.x * ra.x + ra.y * ra.y);
        float ib = rsqrtf(rb.x * rb.x + rb.y * rb.y);
        ra.x *= ia; ra.y *= ia; rb.x *= ib; rb.y *= ib;
        g_fr[i] = make_float4(rb.x * ra.x - rb.y * ra.y,
                              rb.x * ra.y + rb.y * ra.x, rb.x, rb.y);
    }
    if (i == 0) { g_wsum[0] = 0.0f; g_wsum[1] = 0.0f; }

    int warp = threadIdx.x >> 5, lane = threadIdx.x & 31;
    int node = blockIdx.x * 8 + warp;
    if (node < N_NODES) {
        float2 f = ((const float2*)features)[node * HC + lane];
        const float2* W1 = (const float2*)attn1_w;
        float r[4];
#pragma unroll
        for (int k = 0; k < 4; k++) {
            float2 w = W1[k * HC + lane];
            r[k] = w.x * f.x + w.y * f.y;
        }
#pragma unroll
        for (int off = 16; off; off >>= 1)
#pragma unroll
            for (int k = 0; k < 4; k++)
                r[k] += __shfl_xor_sync(0xffffffffu, r[k], off);
        if (lane == 0)
#pragma unroll
            for (int k = 0; k < 4; k++) g_a1[node * 4 + k] = celu3f(r[k]);
    }
}

__global__ void __launch_bounds__(256) pass1_kernel(
    const float* __restrict__ features, const float* __restrict__ attn2,
    const int* __restrict__ inst) {
    int warp = threadIdx.x >> 5, lane = threadIdx.x & 31;
    int e = blockIdx.x * 8 + warp;
    int m = blockIdx.y;
    if (e >= E_EDGES) return;
    const int* ip = inst + (size_t)m * E_EDGES * P_LEN + e * 3;

    float4 fr = g_fr[m * 32 + lane];

    int i0 = ip[0], i1 = ip[1], i2 = ip[2];
    const float2* F = (const float2*)features;
    float2 f0 = F[i0 * HC + lane];
    float2 f1 = F[i1 * HC + lane];
    float2 f2 = F[i2 * HC + lane];

    float mre = (f0.x * fr.x - f0.y * fr.y) + (f1.x * fr.z - f1.y * fr.w) + f2.x;
    float mim = (f0.x * fr.y + f0.y * fr.x) + (f1.x * fr.w + f1.y * fr.z) + f2.y;
    mre *= (1.0f / 3.0f); mim *= (1.0f / 3.0f);

    float se0 = celu3f_fast(mre) * __fdividef(1.0f, 1.0f + __expf(-mre));
    float se1 = celu3f_fast(mim) * __fdividef(1.0f, 1.0f + __expf(-mim));
    float ef0 = celu3f_fast(se0), ef1 = celu3f_fast(se1);

    const float2* W2 = (const float2*)attn2;
    float2 w0 = W2[0 * HC + lane], w1 = W2[1 * HC + lane];
    float2 w2 = W2[2 * HC + lane], w3 = W2[3 * HC + lane];
    float r0 = w0.x * ef0 + w0.y * ef1;
    float r1 = w1.x * ef0 + w1.y * ef1;
    float r2 = w2.x * ef0 + w2.y * ef1;
    float r3 = w3.x * ef0 + w3.y * ef1;
    float tA = __shfl_xor_sync(0xffffffffu, (lane & 1) ? r0 : r1, 1);
    float s01 = ((lane & 1) ? r1 : r0) + tA;
    float tB = __shfl_xor_sync(0xffffffffu, (lane & 1) ? r2 : r3, 1);
    float s23 = ((lane & 1) ? r3 : r2) + tB;
    float tC = __shfl_xor_sync(0xffffffffu, (lane & 2) ? s01 : s23, 2);
    float v = ((lane & 2) ? s23 : s01) + tC;
    v += __shfl_xor_sync(0xffffffffu, v, 4);
    v += __shfl_xor_sync(0xffffffffu, v, 8);
    v += __shfl_xor_sync(0xffffffffu, v, 16);

    float4 a1v = *(const float4*)(g_a1 + (size_t)i0 * 4);
    int hk = lane & 3;
    float a1h = hk == 0 ? a1v.x : hk == 1 ? a1v.y : hk == 2 ? a1v.z : a1v.w;
    float exval = __expf(celu3f_fast(a1h + v));

    size_t rowg = (size_t)m * N_NODES + i0;
    if (lane < 4) atomicAdd(g_den + rowg * 4 + lane, exval);

    int k0 = (lane & 1) * 2;
    int base4 = lane & 28;
    float exa = __shfl_sync(0xffffffffu, exval, base4 | k0);
    float exb = __shfl_sync(0xffffffffu, exval, base4 | (k0 + 1));

    float p0 = __shfl_xor_sync(0xffffffffu, ef0, 1);
    float p1 = __shfl_xor_sync(0xffffffffu, ef1, 1);
    float v0, v1, v2, v3;
    if ((lane & 1) == 0) { v0 = ef0; v1 = ef1; v2 = p0; v3 = p1; }
    else                 { v0 = p0;  v1 = p1;  v2 = ef0; v3 = ef1; }
    int g4 = (lane >> 1) * 4;

    float* base = g_z + rowg * D;
    float* pa = base + k0 * H + g4;
    float* pb = base + (k0 + 1) * H + g4;
    asm volatile("red.global.add.v4.f32 [%0], {%1,%2,%3,%4};" ::
                 "l"(pa), "f"(exa * v0), "f"(exa * v1),
                 "f"(exa * v2), "f"(exa * v3) : "memory");
    asm volatile("red.global.add.v4.f32 [%0], {%1,%2,%3,%4};" ::
                 "l"(pb), "f"(exb * v0), "f"(exb * v1),
                 "f"(exb * v2), "f"(exb * v3) : "memory");
}

// ---- zc = bf16(celu3(z * inv_den)) at full occupancy ------------------------
__global__ void __launch_bounds__(256) zc_kernel() {
    int i = blockIdx.x * blockDim.x + threadIdx.x;   // 16B chunk index
    if (i >= R_TOT * 32) return;
    int row = i >> 5, c = i & 31;
    float d = g_den[(size_t)row * 4 + (c >> 3)];
    float inv = d > 0.0f ? 1.0f / d : 0.0f;
    const float4* zp = (const float4*)(g_z + (size_t)row * 256 + c * 8);
    float4 za = zp[0], zb = zp[1];
    uint4 pk = make_uint4(
        bfpack(celu3f_fast(za.x * inv), celu3f_fast(za.y * inv)),
        bfpack(celu3f_fast(za.z * inv), celu3f_fast(za.w * inv)),
        bfpack(celu3f_fast(zb.x * inv), celu3f_fast(zb.y * inv)),
        bfpack(celu3f_fast(zb.z * inv), celu3f_fast(zb.w * inv)));
    *(uint4*)(g_zc + (size_t)row * 256 + c * 8) = pk;
}

// ---- stage one As tile via cp.async (no commit inside) ---------------------
__device__ __forceinline__ void stage_tile_async(unsigned sbuf, int t, int tid) {
    int r0 = t * 128;
#pragma unroll
    for (int i = tid; i < 4096; i += THREADS_MLP) {
        int r = i >> 5, c = i & 31;
        int gr = r0 + r;
        unsigned off = sbuf + r * 512 + ((unsigned)(c ^ (r & 7)) << 4);
        const void* src = (gr < R_TOT)
            ? (const void*)(g_zc + (size_t)gr * 256 + c * 8)
            : (const void*)g_zc;                    // dummy valid addr
        cp_async16(off, src, (gr < R_TOT) ? 16u : 0u);
    }
    asm volatile("cp.async.commit_group;" ::: "memory");
}

// ---- Fused MLP: cp.async double-buffered As; B1+B2 persistent --------------
__global__ void __launch_bounds__(THREADS_MLP, 1) mlp_fused(
    const float* __restrict__ fw1, const float* __restrict__ fb1,
    const float* __restrict__ fw2, const float* __restrict__ fb2,
    const float* __restrict__ fw3) {
    extern __shared__ char smem[];
    const unsigned sb0 = smem_u32(smem);           // As buffers at 0 / 65536
    const unsigned sbT = sb0 + 131072;             // T1s
    int tid = threadIdx.x, w = tid >> 5, l = tid & 31;
    int lq = l >> 2, lr = l & 3;

    unsigned B1[2][16][2];
#pragma unroll
    for (int nt = 0; nt < 2; nt++) {
        int col = w * 16 + nt * 8 + lq;
#pragma unroll
        for (int kt = 0; kt < 16; kt++) {
            const float* p = fw1 + (size_t)col * 256 + kt * 16 + lr * 2;
            B1[nt][kt][0] = bfpack(p[0], p[1]);
            B1[nt][kt][1] = bfpack(p[8], p[9]);
        }
    }
    unsigned B2[16][2];
    {
        int col = w * 8 + lq;
#pragma unroll
        for (int kt = 0; kt < 16; kt++) {
            const float* p = fw2 + (size_t)col * 256 + kt * 16 + lr * 2;
            B2[kt][0] = bfpack(p[0], p[1]);
            B2[kt][1] = bfpack(p[8], p[9]);
        }
    }
    float fb1c[2][2], fb2c[2], fw3c[2];
#pragma unroll
    for (int nt = 0; nt < 2; nt++) {
        fb1c[nt][0] = fb1[w * 16 + nt * 8 + lr * 2];
        fb1c[nt][1] = fb1[w * 16 + nt * 8 + lr * 2 + 1];
    }
    fb2c[0] = fb2[w * 8 + lr * 2];     fb2c[1] = fb2[w * 8 + lr * 2 + 1];
    fw3c[0] = fw3[w * 8 + lr * 2];     fw3c[1] = fw3[w * 8 + lr * 2 + 1];

    float vs0 = 0.0f, vs1 = 0.0f;

    // prefetch first tile into buffer 0
    stage_tile_async(sb0, blockIdx.x, tid);
    unsigned buf = 0;

    for (int t = blockIdx.x; t < MLP_TILES; t += GRID_MLP) {
        int r0 = t * 128;
        asm volatile("cp.async.wait_group 0;" ::: "memory");
        __syncthreads();                       // As[buf] ready; T1 reads done
        int tn = t + GRID_MLP;
        if (tn < MLP_TILES)
            stage_tile_async(sb0 + (buf ^ 1) * 65536, tn, tid);
        const unsigned sbA = sb0 + buf * 65536;

#pragma unroll 2
        for (int mt = 0; mt < 8; mt++) {
            int m0 = mt * 16;
            float acc[2][4] = {{0.f, 0.f, 0.f, 0.f}, {0.f, 0.f, 0.f, 0.f}};
            int arow = m0 + (l & 15);
#pragma unroll
            for (int kt = 0; kt < 16; kt++) {
                unsigned a[4];
                unsigned ad = sbA + arow * 512 +
                              ((unsigned)((2 * kt + (l >> 4)) ^ (arow & 7)) << 4);
                ldmatrix_x4(a, ad);
                mma_bf16(acc[0], a, B1[0][kt]);
                mma_bf16(acc[1], a, B1[1][kt]);
            }
            int rlo = m0 + lq, rhi = rlo + 8;
#pragma unroll
            for (int nt = 0; nt < 2; nt++) {
                int col = w * 16 + nt * 8 + lr * 2;
                unsigned clo = bfpack(celu3f_fast(acc[nt][0] + fb1c[nt][0]),
                                      celu3f_fast(acc[nt][1] + fb1c[nt][1]));
                unsigned chi = bfpack(celu3f_fast(acc[nt][2] + fb1c[nt][0]),
                                      celu3f_fast(acc[nt][3] + fb1c[nt][1]));
                unsigned olo = 131072 + rlo * 512 +
                               ((unsigned)((col >> 3) ^ (rlo & 7)) << 4) + (col & 7) * 2;
                unsigned ohi = 131072 + rhi * 512 +
                               ((unsigned)((col >> 3) ^ (rhi & 7)) << 4) + (col & 7) * 2;
                *(unsigned*)(smem + olo) = clo;
                *(unsigned*)(smem + ohi) = chi;
            }
        }
        __syncthreads();

#pragma unroll 2
        for (int mt = 0; mt < 8; mt++) {
            int m0 = mt * 16;
            float acc[4] = {0.f, 0.f, 0.f, 0.f};
            int arow = m0 + (l & 15);
#pragma unroll
            for (int kt = 0; kt < 16; kt++) {
                unsigned a[4];
                unsigned ad = sbT + arow * 512 +
                              ((unsigned)((2 * kt + (l >> 4)) ^ (arow & 7)) << 4);
                ldmatrix_x4(a, ad);
                mma_bf16(acc, a, B2[kt]);
            }
            int rlo = r0 + m0 + lq, rhi = rlo + 8;
            float slo = celu3f_fast(acc[0] + fb2c[0]) * fw3c[0] +
                        celu3f_fast(acc[1] + fb2c[1]) * fw3c[1];
            float shi = celu3f_fast(acc[2] + fb2c[0]) * fw3c[0] +
                        celu3f_fast(acc[3] + fb2c[1]) * fw3c[1];
            if (rlo < N_NODES) vs0 += slo; else if (rlo < R_TOT) vs1 += slo;
            if (rhi < N_NODES) vs0 += shi; else if (rhi < R_TOT) vs1 += shi;
        }
        buf ^= 1;
    }

#pragma unroll
    for (int off = 16; off; off >>= 1) {
        vs0 += __shfl_xor_sync(0xffffffffu, vs0, off);
        vs1 += __shfl_xor_sync(0xffffffffu, vs1, off);
    }
    __syncthreads();
    float* red = (float*)smem;
    if (l == 0) { red[w] = vs0; red[16 + w] = vs1; }
    __syncthreads();
    if (tid == 0) {
        float a0 = 0.f, a1 = 0.f;
#pragma unroll
        for (int i = 0; i < 16; i++) { a0 += red[i]; a1 += red[16 + i]; }
        atomicAdd(&g_wsum[0], a0);
        atomicAdd(&g_wsum[1], a1);
    }
}

__global__ void beta_kernel() {
    float w0 = g_wsum[0] * (1.0f / (float)N_NODES);
    float w1 = g_wsum[1] * (1.0f / (float)N_NODES);
    float mx = fmaxf(w0, w1);
    float e0 = expf(w0 - mx), e1 = expf(w1 - mx);
    float inv = 1.0f / (e0 + e1);
    g_beta[0] = e0 * inv;
    g_beta[1] = e1 * inv;
}

__global__ void combine_kernel(float* __restrict__ out) {
    int i = blockIdx.x * blockDim.x + threadIdx.x;
    if (i < N_NODES * D / 4) {
        int f = i * 4;
        int node = f >> 8;
        int head = (f & 255) >> 6;
        float d0 = g_den[(size_t)node * 4 + head];
        float d1 = g_den[(size_t)(N_NODES + node) * 4 + head];
        float inv0 = d0 > 0.0f ? 1.0f / d0 : 0.0f;
        float inv1 = d1 > 0.0f ? 1.0f / d1 : 0.0f;
        float b0 = g_beta[0], b1 = g_beta[1];
        float4 a = ((const float4*)g_z)[i];
        float4 c = ((const float4*)(g_z + (size_t)N_NODES * D))[i];
        float4 o;
        o.x = b0 * celu3f_fast(a.x * inv0) + b1 * celu3f_fast(c.x * inv1);
        o.y = b0 * celu3f_fast(a.y * inv0) + b1 * celu3f_fast(c.y * inv1);
        o.z = b0 * celu3f_fast(a.z * inv0) + b1 * celu3f_fast(c.z * inv1);
        o.w = b0 * celu3f_fast(a.w * inv0) + b1 * celu3f_fast(c.w * inv1);
        ((float4*)out)[i] = o;
    }
}

extern "C" void kernel_launch(void* const* d_in, const int* in_sizes, int n_in,
                              void* d_out, int out_size) {
    const float* features = (const float*)d_in[0];
    const float* r_vec    = (const float*)d_in[1];
    const float* attn1_w  = (const float*)d_in[2];
    const float* attn2    = (const float*)d_in[3];
    const float* fw1      = (const float*)d_in[4];
    const float* fb1      = (const float*)d_in[5];
    const float* fw2      = (const float*)d_in[6];
    const float* fb2      = (const float*)d_in[7];
    const float* fw3      = (const float*)d_in[8];
    const int*   inst     = (const int*)d_in[9];
    float* out = (float*)d_out;

    cudaFuncSetAttribute(mlp_fused,
                         cudaFuncAttributeMaxDynamicSharedMemorySize, SMEM_FUSED);

    prep_kernel<<<(R_TOT * D / 4 + 255) / 256, 256>>>(r_vec, features, attn1_w); // 1
    pass1_kernel<<<dim3(E_EDGES / 8, 2), 256>>>(features, attn2, inst);          // 2
    zc_kernel<<<(R_TOT * 32 + 255) / 256, 256>>>();                              // 3
    mlp_fused<<<GRID_MLP, THREADS_MLP, SMEM_FUSED>>>(fw1, fb1, fw2, fb2, fw3);   // 4 (ncu)
    beta_kernel<<<1, 1>>>();                                                     // 5
    combine_kernel<<<(N_NODES * D / 4 + 255) / 256, 256>>>(out);                 // 6
}